// round 17
// baseline (speedup 1.0000x reference)
#include <cuda_runtime.h>
#include <cuda_fp16.h>

// Problem constants (from reference): L=131072, D=512, B=512, S=512
#define LQ 131072
#define DQ 512
#define SQ 512
#define CAP 24          // slots per label row; Poisson(2) => P(cnt>24) ~ 1e-18

// ---- static scratch (no runtime allocation; zero-initialized at load) ----
// g_count is SELF-CLEANING: score_kernel resets each row to 0 after reading,
// so every kernel_launch invocation (and every graph replay) starts from zeros.
__device__ int    g_count[LQ];                // refs per label
__device__ int    g_slots[(size_t)LQ * CAP];  // packed (b<<16)|s per label
__device__ __half g_Xh   [512 * DQ];          // fp16 input rows (512 KB, L2-resident)
__device__ float  g_sa   [DQ];                // sigmoid(alpha)
__device__ float  g_sb   [DQ];                // sigmoid(beta)

// ---------------------------------------------------------------------------
// dtype detection (shortlist may be int32 or int64; true indices < 2^17 so
// int64 high words are all zero; int32 packing puts a random index there)
// ---------------------------------------------------------------------------
__device__ __forceinline__ bool detect_is32(const void* sl, int lane) {
    const unsigned long long* slu = (const unsigned long long*)sl;
    unsigned int hi = (unsigned int)(slu[lane] >> 32);
    hi = __reduce_or_sync(0xffffffffu, hi);
    return hi != 0u;
}

// ---------------------------------------------------------------------------
// Kernel A (prep): blocks [0,1024) bucket the shortlist into per-label slots;
// blocks [1024,1152) build sigmoid LUTs + fp16 input rows.
// ---------------------------------------------------------------------------
__global__ __launch_bounds__(256)
void prep_kernel(const void* __restrict__ shortlist,
                 const float* __restrict__ input,
                 const float* __restrict__ alpha,
                 const float* __restrict__ beta) {
    const int bid = blockIdx.x;
    if (bid < 1024) {
        const int lane = threadIdx.x & 31;
        const bool is32 = detect_is32(shortlist, lane);
        const int t = bid * 256 + threadIdx.x;       // flat = b*SQ + s
        const int idx = is32 ? ((const int*)shortlist)[t]
                             : (int)((const long long*)shortlist)[t];
        const int pair = ((t >> 9) << 16) | (t & (SQ - 1)); // (b<<16)|s
        const int pos = atomicAdd(&g_count[idx], 1);
        if (pos < CAP)
            g_slots[(size_t)idx * CAP + pos] = pair;
        // cnt > CAP rows are recomputed from the shortlist in score_kernel.
        return;
    }
    const int t = (bid - 1024) * 256 + threadIdx.x;  // 32768 threads
    if (t < DQ) {
        g_sa[t] = 1.0f / (1.0f + __expf(-alpha[t]));
        g_sb[t] = 1.0f / (1.0f + __expf(-beta[t]));
    }
    const long long base = (long long)t * 8;         // 8 floats -> 8 halfs
    const float4* x4 = reinterpret_cast<const float4*>(input + base);
    float4 a = x4[0], b = x4[1];
    __half2 h0 = __floats2half2_rn(a.x, a.y);
    __half2 h1 = __floats2half2_rn(a.z, a.w);
    __half2 h2 = __floats2half2_rn(b.x, b.y);
    __half2 h3 = __floats2half2_rn(b.z, b.w);
    uint4 o;
    o.x = *reinterpret_cast<unsigned int*>(&h0);
    o.y = *reinterpret_cast<unsigned int*>(&h1);
    o.z = *reinterpret_cast<unsigned int*>(&h2);
    o.w = *reinterpret_cast<unsigned int*>(&h3);
    reinterpret_cast<uint4*>(g_Xh)[t] = o;
}

// ---------------------------------------------------------------------------
// Kernel B (score): ONE-SHOT warp=row (R11 structure — beats persistent), but
// the combined row c is staged in SHARED memory (2 KB/warp) instead of 16
// registers, and W/V stream in two 4-LDG batches. Peak register live-set ~30
// -> __launch_bounds__(256, 8) targets 64 resident warps/SM (100% occupancy).
// Warp-contiguous addressing everywhere: every LDG/LDS covers a contiguous
// span (minimal L1tex wavefronts — the R13 lesson).
// ---------------------------------------------------------------------------
__device__ __forceinline__ float dot4h(uint2 u, float4 c) {
    __half2 h0 = *reinterpret_cast<__half2*>(&u.x);
    __half2 h1 = *reinterpret_cast<__half2*>(&u.y);
    float2 f0 = __half22float2(h0), f1 = __half22float2(h1);
    return f0.x * c.x + f0.y * c.y + f1.x * c.z + f1.y * c.w;
}

__global__ __launch_bounds__(256, 8)
void score_kernel(const float* __restrict__ W,       // weight [L, D]
                  const float* __restrict__ V,       // labels [L, D]
                  const float* __restrict__ bias,    // [L]
                  const void*  __restrict__ shortlist,
                  float* __restrict__ out)           // [B, S]
{
    __shared__ float s_c[8][DQ];                     // 16 KB: per-warp combined row

    const int warp = threadIdx.x >> 5;
    const int lane = threadIdx.x & 31;
    const int row  = blockIdx.x * 8 + warp;

    const int cnt = g_count[row];
    if (lane == 0 && cnt != 0) g_count[row] = 0;     // self-clean for next launch
    if (cnt == 0) return;                            // warp-uniform; no block sync used

    const int* slots = g_slots + (size_t)row * CAP;

    // Hoist first pair words: independent of the W/V DRAM stream.
    int p0 = slots[0];
    int p1 = (cnt > 1) ? slots[1] : 0;
    const float bs = bias[row];

    const float4* w4  = reinterpret_cast<const float4*>(W + (size_t)row * DQ);
    const float4* v4  = reinterpret_cast<const float4*>(V + (size_t)row * DQ);
    const float4* sa4 = reinterpret_cast<const float4*>(g_sa);
    const float4* sb4 = reinterpret_cast<const float4*>(g_sb);
    float4* c4 = reinterpret_cast<float4*>(s_c[warp]);

    // Batch A: units {lane, lane+32}; Batch B: units {lane+64, lane+96}.
    // 4 DRAM loads in flight per batch, c chunks retired to smem immediately
    // (keeps register live-set small for the (256,8) occupancy target).
    {
        float4 wA = __ldcs(w4 + lane), wB = __ldcs(w4 + lane + 32);
        float4 vA = __ldcs(v4 + lane), vB = __ldcs(v4 + lane + 32);
        float4 aA = sa4[lane], bA = sb4[lane];
        c4[lane] = make_float4(aA.x*wA.x + bA.x*vA.x, aA.y*wA.y + bA.y*vA.y,
                               aA.z*wA.z + bA.z*vA.z, aA.w*wA.w + bA.w*vA.w);
        float4 aB = sa4[lane + 32], bB = sb4[lane + 32];
        c4[lane + 32] = make_float4(aB.x*wB.x + bB.x*vB.x, aB.y*wB.y + bB.y*vB.y,
                                    aB.z*wB.z + bB.z*vB.z, aB.w*wB.w + bB.w*vB.w);
    }
    {
        float4 wA = __ldcs(w4 + lane + 64), wB = __ldcs(w4 + lane + 96);
        float4 vA = __ldcs(v4 + lane + 64), vB = __ldcs(v4 + lane + 96);
        float4 aA = sa4[lane + 64], bA = sb4[lane + 64];
        c4[lane + 64] = make_float4(aA.x*wA.x + bA.x*vA.x, aA.y*wA.y + bA.y*vA.y,
                                    aA.z*wA.z + bA.z*vA.z, aA.w*wA.w + bA.w*vA.w);
        float4 aB = sa4[lane + 96], bB = sb4[lane + 96];
        c4[lane + 96] = make_float4(aB.x*wB.x + bB.x*vB.x, aB.y*wB.y + bB.y*vB.y,
                                    aB.z*wB.z + bB.z*vB.z, aB.w*wB.w + bB.w*vB.w);
    }
    __syncwarp();   // smem c visible warp-wide (each lane reads others' chunks)

    if (cnt <= CAP) {
        int i = 0;
        for (; i + 2 <= cnt; i += 2) {
            const int b0i = p0 >> 16, s0 = p0 & 0xffff;
            const int b1i = p1 >> 16, s1 = p1 & 0xffff;
            const uint2* x0 = reinterpret_cast<const uint2*>(g_Xh + (size_t)b0i * DQ);
            const uint2* x1 = reinterpret_cast<const uint2*>(g_Xh + (size_t)b1i * DQ);

            uint2 u00 = x0[lane], u01 = x0[lane + 32], u02 = x0[lane + 64], u03 = x0[lane + 96];
            uint2 u10 = x1[lane], u11 = x1[lane + 32], u12 = x1[lane + 64], u13 = x1[lane + 96];

            if (i + 2 < cnt) {                       // prefetch next pair words
                p0 = slots[i + 2];
                p1 = (i + 3 < cnt) ? slots[i + 3] : 0;
            }

            float4 cc;
            float r0, r1;
            cc = c4[lane];      r0  = dot4h(u00, cc); r1  = dot4h(u10, cc);
            cc = c4[lane + 32]; r0 += dot4h(u01, cc); r1 += dot4h(u11, cc);
            cc = c4[lane + 64]; r0 += dot4h(u02, cc); r1 += dot4h(u12, cc);
            cc = c4[lane + 96]; r0 += dot4h(u03, cc); r1 += dot4h(u13, cc);

            #pragma unroll
            for (int o = 16; o > 0; o >>= 1) {
                r0 += __shfl_xor_sync(0xffffffffu, r0, o);
                r1 += __shfl_xor_sync(0xffffffffu, r1, o);
            }
            if (lane == 0) {
                out[b0i * SQ + s0] = r0 + bs;
                out[b1i * SQ + s1] = r1 + bs;
            }
        }
        if (i < cnt) {
            const int b0i = p0 >> 16, s0 = p0 & 0xffff;
            const uint2* x0 = reinterpret_cast<const uint2*>(g_Xh + (size_t)b0i * DQ);
            uint2 u00 = x0[lane], u01 = x0[lane + 32], u02 = x0[lane + 64], u03 = x0[lane + 96];
            float r0 = dot4h(u00, c4[lane])      + dot4h(u01, c4[lane + 32])
                     + dot4h(u02, c4[lane + 64]) + dot4h(u03, c4[lane + 96]);
            #pragma unroll
            for (int o = 16; o > 0; o >>= 1)
                r0 += __shfl_xor_sync(0xffffffffu, r0, o);
            if (lane == 0)
                out[b0i * SQ + s0] = r0 + bs;
        }
    } else {
        // Overflow safety net (statistically never taken): the stored slot
        // subset is nondeterministic, so recompute ALL refs of this row by
        // rescanning the shortlist. Each ref's output is independent.
        const bool is32 = detect_is32(shortlist, lane);
        const int*       sl32 = (const int*)shortlist;
        const long long* sl64 = (const long long*)shortlist;
        #pragma unroll 1
        for (int t = 0; t < 512 * SQ; t++) {
            const int idx = is32 ? sl32[t] : (int)sl64[t];
            if (idx != row) continue;
            const int b0i = t >> 9, s0 = t & (SQ - 1);
            const uint2* x0 = reinterpret_cast<const uint2*>(g_Xh + (size_t)b0i * DQ);
            uint2 u00 = x0[lane], u01 = x0[lane + 32], u02 = x0[lane + 64], u03 = x0[lane + 96];
            float r0 = dot4h(u00, c4[lane])      + dot4h(u01, c4[lane + 32])
                     + dot4h(u02, c4[lane + 64]) + dot4h(u03, c4[lane + 96]);
            #pragma unroll
            for (int o = 16; o > 0; o >>= 1)
                r0 += __shfl_xor_sync(0xffffffffu, r0, o);
            if (lane == 0)
                out[b0i * SQ + s0] = r0 + bs;
        }
    }
}

extern "C" void kernel_launch(void* const* d_in, const int* in_sizes, int n_in,
                              void* d_out, int out_size) {
    const float* input     = (const float*)d_in[0];      // [B, D]
    const float* labels    = (const float*)d_in[1];      // [L, D]  (v)
    const float* weight    = (const float*)d_in[2];      // [L, D]  (u)
    const float* alpha     = (const float*)d_in[3];      // [1, D]
    const float* beta      = (const float*)d_in[4];      // [1, D]
    const float* bias      = (const float*)d_in[5];      // [L]
    const void*  shortlist = d_in[6];                    // [B, S] int32 or int64
    float*       out       = (float*)d_out;              // [B, S]

    prep_kernel<<<1152, 256>>>(shortlist, input, alpha, beta);
    score_kernel<<<LQ / 8, 256>>>(weight, labels, bias, shortlist, out);
}